// round 2
// baseline (speedup 1.0000x reference)
#include <cuda_runtime.h>
#include <cuda_bf16.h>
#include <cstdint>

// ---------------------------------------------------------------------------
// GradientLayerPoisson: 2nd-order forward jet through tanh MLP 2->256->256->256->1
// out = [u(B) | du/dx0(B) | d2u/dx0^2(B)]
//
// Fully fused: one block processes 32 samples end-to-end, activations jet
// (h, h', h'') ping-pongs between two SMEM buffers. GEMMs use packed
// fp32x2 FFMA (fma.rn.f32x2) for 2x fp32 throughput.
// ---------------------------------------------------------------------------

#define HID 256
#define TS 32            // samples per block
#define HPAD 257         // row pad: stride 257 -> conflict-free (s*257+k)%32
#define HBUF (3*TS*HPAD) // one jet buffer (floats)

#define HIDX(st, s, u) (((st)*TS + (s))*HPAD + (u))

__device__ __forceinline__ unsigned long long pack2(float x) {
    unsigned long long r;
    asm("mov.b64 %0, {%1, %1};" : "=l"(r) : "f"(x));
    return r;
}

__device__ __forceinline__ unsigned long long ffma2(unsigned long long a,
                                                    unsigned long long b,
                                                    unsigned long long c) {
    unsigned long long d;
    asm("fma.rn.f32x2 %0, %1, %2, %3;" : "=l"(d) : "l"(a), "l"(b), "l"(c));
    return d;
}

__device__ __forceinline__ void unpack2(unsigned long long v, float& lo, float& hi) {
    asm("mov.b64 {%0, %1}, %2;" : "=f"(lo), "=f"(hi) : "l"(v));
}

// tanh + sech^2 via EX2 + approx-rcp + 1 Newton step.
// tanh(x) = 1 - 2/(1+e^{2x});  1 - tanh^2 = 4 r (1 - r),  r = 1/(1+e^{2x})
__device__ __forceinline__ void tanh_d(float x, float& a, float& s2) {
    x = fminf(fmaxf(x, -15.f), 15.f);
    float t = exp2f(x * 2.8853900817779268f);  // e^{2x}
    float d = 1.f + t;
    float r;
    asm("rcp.approx.ftz.f32 %0, %1;" : "=f"(r) : "f"(d));
    r = r * (2.f - d * r);     // Newton refine -> ~fp32 accurate
    a  = 1.f - 2.f * r;
    s2 = 4.f * r * (1.f - r);
}

// GEMM: dst[st][s][:] = src[st][s][:] @ W   (3 jet streams, shared W)
// 256 threads: lane s = t&31 (sample), ug = t>>5 (8 units of the 64-unit tile)
__device__ __forceinline__ void jet_gemm(const float* __restrict__ Wg,
                                         const float* __restrict__ src,
                                         float* __restrict__ dst,
                                         float* __restrict__ WS, int t) {
    const int s  = t & 31;
    const int ug = t >> 5;
    #pragma unroll 1
    for (int tile = 0; tile < 4; ++tile) {
        const int u0 = tile * 64;
        unsigned long long acc[12];
        #pragma unroll
        for (int i = 0; i < 12; ++i) acc[i] = 0ull;

        #pragma unroll 1
        for (int kk = 0; kk < HID; kk += 64) {
            __syncthreads();  // protect WS reuse
            // stage W[kk..kk+64)[u0..u0+64) -> WS[64][64]
            #pragma unroll
            for (int r = 0; r < 4; ++r) {
                int f  = t + 256 * r;       // float4 index, 1024 total
                int kr = f >> 4;
                int c4 = f & 15;
                ((float4*)WS)[f] =
                    *(const float4*)(&Wg[(kk + kr) * HID + u0 + c4 * 4]);
            }
            __syncthreads();

            #pragma unroll 8
            for (int k = 0; k < 64; ++k) {
                float h0 = src[HIDX(0, s, kk + k)];
                float h1 = src[HIDX(1, s, kk + k)];
                float h2 = src[HIDX(2, s, kk + k)];
                unsigned long long hp0 = pack2(h0);
                unsigned long long hp1 = pack2(h1);
                unsigned long long hp2 = pack2(h2);
                const ulonglong2* wp =
                    (const ulonglong2*)(WS + k * 64 + ug * 8);
                ulonglong2 wa = wp[0];
                ulonglong2 wb = wp[1];
                acc[0]  = ffma2(hp0, wa.x, acc[0]);
                acc[1]  = ffma2(hp0, wa.y, acc[1]);
                acc[2]  = ffma2(hp0, wb.x, acc[2]);
                acc[3]  = ffma2(hp0, wb.y, acc[3]);
                acc[4]  = ffma2(hp1, wa.x, acc[4]);
                acc[5]  = ffma2(hp1, wa.y, acc[5]);
                acc[6]  = ffma2(hp1, wb.x, acc[6]);
                acc[7]  = ffma2(hp1, wb.y, acc[7]);
                acc[8]  = ffma2(hp2, wa.x, acc[8]);
                acc[9]  = ffma2(hp2, wa.y, acc[9]);
                acc[10] = ffma2(hp2, wb.x, acc[10]);
                acc[11] = ffma2(hp2, wb.y, acc[11]);
            }
        }
        // store raw z (bias added in tanh phase)
        #pragma unroll
        for (int st = 0; st < 3; ++st)
            #pragma unroll
            for (int p = 0; p < 4; ++p) {
                float lo, hi;
                unpack2(acc[st * 4 + p], lo, hi);
                int u = u0 + ug * 8 + 2 * p;
                dst[HIDX(st, s, u)]     = lo;
                dst[HIDX(st, s, u + 1)] = hi;
            }
    }
}

// elementwise tanh-jet (in place), thread t owns unit j=t for all samples
__device__ __forceinline__ void tanh_phase(float* __restrict__ Z,
                                           const float* __restrict__ bias,
                                           int t) {
    float bb = bias[t];
    #pragma unroll 4
    for (int i = 0; i < TS; ++i) {
        float z  = Z[HIDX(0, i, t)] + bb;
        float z1 = Z[HIDX(1, i, t)];
        float z2 = Z[HIDX(2, i, t)];
        float a, s2;
        tanh_d(z, a, s2);
        float a1 = s2 * z1;
        float a2 = s2 * z2 - 2.f * a * a1 * z1;
        Z[HIDX(0, i, t)] = a;
        Z[HIDX(1, i, t)] = a1;
        Z[HIDX(2, i, t)] = a2;
    }
}

extern "C" __global__ void __launch_bounds__(256, 1)
pinn_jet_kernel(const float* __restrict__ x,
                const float* __restrict__ W1, const float* __restrict__ b1,
                const float* __restrict__ W2, const float* __restrict__ b2,
                const float* __restrict__ W3, const float* __restrict__ b3,
                const float* __restrict__ W4, const float* __restrict__ b4,
                float* __restrict__ out, int B) {
    extern __shared__ float smem[];
    float* HA = smem;
    float* HB = HA + HBUF;
    float* WS = HB + HBUF;  // 64*64 floats, also reused to stage x

    const int t  = threadIdx.x;
    const int bs = blockIdx.x * TS;  // first sample of this block

    // ---- layer 1: x(2) -> HID, jet seeds: z' = W1[0,:], z'' = 0 ----
    if (t < TS) {
        float2 xv = ((const float2*)x)[bs + t];
        WS[2 * t]     = xv.x;
        WS[2 * t + 1] = xv.y;
    }
    __syncthreads();
    {
        const int j = t;  // unit
        float c0 = W1[j];
        float c1 = W1[HID + j];
        float bb = b1[j];
        #pragma unroll 4
        for (int i = 0; i < TS; ++i) {
            float z = fmaf(WS[2 * i], c0, fmaf(WS[2 * i + 1], c1, bb));
            float a, s2;
            tanh_d(z, a, s2);
            float a1 = s2 * c0;                 // (1-a^2) * z'   (z' = c0)
            float a2 = -2.f * a * a1 * c0;      // z'' = 0
            HA[HIDX(0, i, j)] = a;
            HA[HIDX(1, i, j)] = a1;
            HA[HIDX(2, i, j)] = a2;
        }
    }
    __syncthreads();

    // ---- layer 2 ----
    jet_gemm(W2, HA, HB, WS, t);
    __syncthreads();
    tanh_phase(HB, b2, t);
    __syncthreads();

    // ---- layer 3 ----
    jet_gemm(W3, HB, HA, WS, t);
    __syncthreads();
    tanh_phase(HA, b3, t);
    __syncthreads();

    // ---- output layer: dot with W4 (HID x 1) per jet stream ----
    if (t < 96) {
        const int st = t >> 5;
        const int s  = t & 31;
        float sum = 0.f;
        #pragma unroll 8
        for (int j = 0; j < HID; ++j)
            sum = fmaf(HA[HIDX(st, s, j)], W4[j], sum);
        if (st == 0) sum += b4[0];
        out[st * B + bs + s] = sum;
    }
}

extern "C" void kernel_launch(void* const* d_in, const int* in_sizes, int n_in,
                              void* d_out, int out_size) {
    const float* x  = (const float*)d_in[0];
    const float* W1 = (const float*)d_in[1];
    const float* b1 = (const float*)d_in[2];
    const float* W2 = (const float*)d_in[3];
    const float* b2 = (const float*)d_in[4];
    const float* W3 = (const float*)d_in[5];
    const float* b3 = (const float*)d_in[6];
    const float* W4 = (const float*)d_in[7];
    const float* b4 = (const float*)d_in[8];
    float* out = (float*)d_out;

    const int B = in_sizes[0] / 2;  // x is (B, 2)
    const size_t smem = (size_t)(2 * HBUF + 64 * 64) * sizeof(float);

    cudaFuncSetAttribute(pinn_jet_kernel,
                         cudaFuncAttributeMaxDynamicSharedMemorySize,
                         (int)smem);

    pinn_jet_kernel<<<B / TS, 256, smem>>>(x, W1, b1, W2, b2, W3, b3, W4, b4,
                                           out, B);
}

// round 6
// speedup vs baseline: 2.1548x; 2.1548x over previous
#include <cuda_runtime.h>
#include <cuda_bf16.h>
#include <cstdint>

// GradientLayerPoisson: tanh-MLP 2->256->256->256->1 second-order jet (u, u_x0, u_x0x0)
// via mma.sync bf16 3-term split GEMMs (hh + hl + lh), fully fused per 32 samples.

#define HID  256
#define RS   132        // H row stride in 8B {hi,lo} pairs  (132 mod 16 == 4)
#define BSN  264        // W plane row stride in 4B words    (264 mod 32 == 8)
#define BPLW (32*BSN)   // words per W plane (one K-chunk of 64)

// SMEM byte offsets
#define SM_H    0
#define SM_B    101376                  // H = 96 rows * 132 pairs * 8B
#define SM_BIAS (SM_B + 2*BPLW*4)       // 101376 + 67584 = 168960
#define SM_W4   (SM_BIAS + 2048)        // 171008
#define SM_X    (SM_W4 + 1024)          // 172032
#define SM_OUT  (SM_X + 256)            // 172288
#define SM_TOT  (SM_OUT + 384)          // 172672

__device__ __forceinline__ void tanh_d(float x, float& a, float& s2) {
    x = fminf(fmaxf(x, -15.f), 15.f);
    float t = exp2f(x * 2.8853900817779268f);
    float d = 1.f + t, r;
    asm("rcp.approx.ftz.f32 %0, %1;" : "=f"(r) : "f"(d));
    r = r * (2.f - d * r);
    a  = 1.f - 2.f * r;
    s2 = 4.f * r * (1.f - r);
}

// pack (x,y) -> hi word {bf16(x),bf16(y)} and lo word of residuals
__device__ __forceinline__ void pk2(float x, float y, uint32_t& hi, uint32_t& lo) {
    __nv_bfloat16 hx = __float2bfloat16_rn(x);
    __nv_bfloat16 hy = __float2bfloat16_rn(y);
    __nv_bfloat16 lx = __float2bfloat16_rn(x - __bfloat162float(hx));
    __nv_bfloat16 ly = __float2bfloat16_rn(y - __bfloat162float(hy));
    hi = (uint32_t)__bfloat16_as_ushort(hx) | ((uint32_t)__bfloat16_as_ushort(hy) << 16);
    lo = (uint32_t)__bfloat16_as_ushort(lx) | ((uint32_t)__bfloat16_as_ushort(ly) << 16);
}

#define MMA(Dx, A, Bp)                                                          \
    asm volatile("mma.sync.aligned.m16n8k16.row.col.f32.bf16.bf16.f32 "         \
                 "{%0,%1,%2,%3},{%4,%5,%6,%7},{%8,%9},{%0,%1,%2,%3};"           \
                 : "+f"((Dx)[0]), "+f"((Dx)[1]), "+f"((Dx)[2]), "+f"((Dx)[3])   \
                 : "r"((A)[0]), "r"((A)[1]), "r"((A)[2]), "r"((A)[3]),          \
                   "r"((Bp)[0]), "r"((Bp)[1]))

extern "C" __global__ void __launch_bounds__(256, 1)
pinn_mma_kernel(const float* __restrict__ x,
                const float* __restrict__ W1, const float* __restrict__ b1,
                const float* __restrict__ W2, const float* __restrict__ b2,
                const float* __restrict__ W3, const float* __restrict__ b3,
                const float* __restrict__ W4, const float* __restrict__ b4,
                float* __restrict__ out, int B) {
    extern __shared__ unsigned char smem[];
    uint2*    Hb     = (uint2*)(smem + SM_H);          // {hi,lo} pairs
    uint32_t* Whi    = (uint32_t*)(smem + SM_B);
    uint32_t* Wlo    = Whi + BPLW;
    float*    biasSm = (float*)(smem + SM_BIAS);        // [2][256]
    float*    w4Sm   = (float*)(smem + SM_W4);
    float2*   xSm    = (float2*)(smem + SM_X);
    float*    outSm  = (float*)(smem + SM_OUT);         // [3][32]

    const int t = threadIdx.x, lane = t & 31, w = t >> 5;
    const int bs = blockIdx.x * 32;

    if (t < 96) outSm[t] = 0.f;
    if (t < 32) xSm[t] = ((const float2*)x)[bs + t];
    biasSm[t]       = b2[t];
    biasSm[256 + t] = b3[t];
    w4Sm[t] = W4[t];
    __syncthreads();

    // ---- layer 1: jets into H (z' = W1[0][u], z'' = 0) ----
    {
        const int up = t & 127, sh = t >> 7;        // unit pair, sample half
        float2 c0 = ((const float2*)W1)[up];        // W1[0][u0], W1[0][u1]
        float2 c1 = ((const float2*)(W1 + HID))[up];
        float2 bb = ((const float2*)b1)[up];
        #pragma unroll 4
        for (int i = 0; i < 16; ++i) {
            int s = sh * 16 + i;
            float2 xv = xSm[s];
            float a0, s20, a1u0, a2u0, a0b, s21, a1u1, a2u1;
            tanh_d(fmaf(xv.x, c0.x, fmaf(xv.y, c1.x, bb.x)), a0, s20);
            tanh_d(fmaf(xv.x, c0.y, fmaf(xv.y, c1.y, bb.y)), a0b, s21);
            a1u0 = s20 * c0.x;  a2u0 = -2.f * a0  * a1u0 * c0.x;
            a1u1 = s21 * c0.y;  a2u1 = -2.f * a0b * a1u1 * c0.y;
            uint32_t h, lo2;
            pk2(a0, a0b, h, lo2);   Hb[(0 * 32 + s) * RS + up] = make_uint2(h, lo2);
            pk2(a1u0, a1u1, h, lo2);Hb[(1 * 32 + s) * RS + up] = make_uint2(h, lo2);
            pk2(a2u0, a2u1, h, lo2);Hb[(2 * 32 + s) * RS + up] = make_uint2(h, lo2);
        }
    }

    float D[3][2][4][4];
    float ps[2][2][3];   // last-layer partials [mt][rowhalf][stream]

    #pragma unroll 1
    for (int l = 0; l < 2; ++l) {
        const float* Wsrc = l ? W3 : W2;
        #pragma unroll
        for (int a = 0; a < 3; ++a)
            #pragma unroll
            for (int b_ = 0; b_ < 2; ++b_)
                #pragma unroll
                for (int c = 0; c < 4; ++c)
                    #pragma unroll
                    for (int d = 0; d < 4; ++d) D[a][b_][c][d] = 0.f;

        #pragma unroll 1
        for (int kc = 0; kc < 4; ++kc) {
            __syncthreads();
            // stage W chunk [64k x 256u] -> packed bf16 hi/lo planes [kp][n]
            #pragma unroll
            for (int i = 0; i < 8; ++i) {
                int q = t + (i << 8);
                int quad = q & 63, kp = q >> 6;
                const float4* g = (const float4*)Wsrc;
                float4 r0 = g[(kc * 64 + 2 * kp) * 64 + quad];
                float4 r1 = g[(kc * 64 + 2 * kp) * 64 + 64 + quad];
                uint32_t hw0, lw0, hw1, lw1, hw2, lw2, hw3, lw3;
                pk2(r0.x, r1.x, hw0, lw0);
                pk2(r0.y, r1.y, hw1, lw1);
                pk2(r0.z, r1.z, hw2, lw2);
                pk2(r0.w, r1.w, hw3, lw3);
                *(uint4*)(Whi + kp * BSN + 4 * quad) = make_uint4(hw0, hw1, hw2, hw3);
                *(uint4*)(Wlo + kp * BSN + 4 * quad) = make_uint4(lw0, lw1, lw2, lw3);
            }
            __syncthreads();

            #pragma unroll
            for (int ks = 0; ks < 4; ++ks) {
                const int kpl = ks * 8 + (lane & 3);
                uint32_t Bh[4][2], Bl[4][2];
                #pragma unroll
                for (int nt = 0; nt < 4; ++nt) {
                    int n = (w << 5) + (nt << 3) + (lane >> 2);
                    Bh[nt][0] = Whi[kpl * BSN + n];
                    Bh[nt][1] = Whi[(kpl + 4) * BSN + n];
                    Bl[nt][0] = Wlo[kpl * BSN + n];
                    Bl[nt][1] = Wlo[(kpl + 4) * BSN + n];
                }
                const int kp = (kc * 4 + ks) * 8 + (lane & 3);
                #pragma unroll
                for (int mt = 0; mt < 2; ++mt) {
                    const int row0 = (mt << 4) + (lane >> 2);
                    #pragma unroll
                    for (int st = 0; st < 3; ++st) {
                        int base = (st * 32 + row0) * RS + kp;
                        uint2 p00 = Hb[base];
                        uint2 p10 = Hb[base + 8 * RS];
                        uint2 p01 = Hb[base + 4];
                        uint2 p11 = Hb[base + 8 * RS + 4];
                        uint32_t Ah[4] = {p00.x, p10.x, p01.x, p11.x};
                        uint32_t Al[4] = {p00.y, p10.y, p01.y, p11.y};
                        #pragma unroll
                        for (int nt = 0; nt < 4; ++nt) {
                            MMA(D[st][mt][nt], Ah, Bh[nt]);
                            MMA(D[st][mt][nt], Ah, Bl[nt]);
                            MMA(D[st][mt][nt], Al, Bh[nt]);
                        }
                    }
                }
            }
        }
        __syncthreads();   // everyone done reading H/W before epilogue rewrites H

        // ---- jet epilogue ----
        if (l == 1) {
            #pragma unroll
            for (int a = 0; a < 2; ++a)
                #pragma unroll
                for (int b_ = 0; b_ < 2; ++b_)
                    #pragma unroll
                    for (int c = 0; c < 3; ++c) ps[a][b_][c] = 0.f;
        }
        #pragma unroll
        for (int mt = 0; mt < 2; ++mt) {
            #pragma unroll
            for (int nt = 0; nt < 4; ++nt) {
                const int u0 = (w << 5) + (nt << 3) + ((lane & 3) << 1);
                float2 bb = *(const float2*)(biasSm + (l ? 256 : 0) + u0);
                float2 w4v = *(const float2*)(w4Sm + u0);
                float av[4], a1v[4], a2v[4];
                #pragma unroll
                for (int p = 0; p < 4; ++p) {
                    float z  = D[0][mt][nt][p] + ((p & 1) ? bb.y : bb.x);
                    float z1 = D[1][mt][nt][p];
                    float z2 = D[2][mt][nt][p];
                    float a, s2;
                    tanh_d(z, a, s2);
                    av[p]  = a;
                    a1v[p] = s2 * z1;
                    a2v[p] = s2 * z2 - 2.f * a * a1v[p] * z1;
                }
                if (l == 0) {
                    const int r0 = (mt << 4) + (lane >> 2);
                    const int pi = (w << 4) + (nt << 2) + (lane & 3);
                    uint32_t h, lo2;
                    pk2(av[0],  av[1],  h, lo2); Hb[(0*32 + r0    ) * RS + pi] = make_uint2(h, lo2);
                    pk2(av[2],  av[3],  h, lo2); Hb[(0*32 + r0 + 8) * RS + pi] = make_uint2(h, lo2);
                    pk2(a1v[0], a1v[1], h, lo2); Hb[(1*32 + r0    ) * RS + pi] = make_uint2(h, lo2);
                    pk2(a1v[2], a1v[3], h, lo2); Hb[(1*32 + r0 + 8) * RS + pi] = make_uint2(h, lo2);
                    pk2(a2v[0], a2v[1], h, lo2); Hb[(2*32 + r0    ) * RS + pi] = make_uint2(h, lo2);
                    pk2(a2v[2], a2v[3], h, lo2); Hb[(2*32 + r0 + 8) * RS + pi] = make_uint2(h, lo2);
                } else {
                    #pragma unroll
                    for (int p = 0; p < 4; ++p) {
                        float wv = (p & 1) ? w4v.y : w4v.x;
                        int rh = p >> 1;
                        ps[mt][rh][0] += av[p]  * wv;
                        ps[mt][rh][1] += a1v[p] * wv;
                        ps[mt][rh][2] += a2v[p] * wv;
                    }
                }
            }
        }
        if (l == 1) {
            #pragma unroll
            for (int mt = 0; mt < 2; ++mt)
                #pragma unroll
                for (int rh = 0; rh < 2; ++rh)
                    #pragma unroll
                    for (int st = 0; st < 3; ++st) {
                        float v = ps[mt][rh][st];
                        v += __shfl_xor_sync(0xffffffffu, v, 1);
                        v += __shfl_xor_sync(0xffffffffu, v, 2);
                        if ((lane & 3) == 0)
                            atomicAdd(&outSm[st * 32 + mt * 16 + (lane >> 2) + rh * 8], v);
                    }
        }
    }

    __syncthreads();
    if (t < 96) {
        int st = t >> 5, s = t & 31;
        float v = outSm[t] + (st == 0 ? b4[0] : 0.f);
        out[st * B + bs + s] = v;
    }
}

extern "C" void kernel_launch(void* const* d_in, const int* in_sizes, int n_in,
                              void* d_out, int out_size) {
    const float* x  = (const float*)d_in[0];
    const float* W1 = (const float*)d_in[1];
    const float* b1 = (const float*)d_in[2];
    const float* W2 = (const float*)d_in[3];
    const float* b2 = (const float*)d_in[4];
    const float* W3 = (const float*)d_in[5];
    const float* b3 = (const float*)d_in[6];
    const float* W4 = (const float*)d_in[7];
    const float* b4 = (const float*)d_in[8];
    float* out = (float*)d_out;
    const int B = in_sizes[0] / 2;

    cudaFuncSetAttribute(pinn_mma_kernel,
                         cudaFuncAttributeMaxDynamicSharedMemorySize, SM_TOT);
    pinn_mma_kernel<<<B / 32, 256, SM_TOT>>>(x, W1, b1, W2, b2, W3, b3, W4, b4,
                                             out, B);
}

// round 7
// speedup vs baseline: 2.5073x; 1.1636x over previous
#include <cuda_runtime.h>
#include <cuda_bf16.h>
#include <cstdint>

// GradientLayerPoisson: tanh-MLP 2->256->256->256->1 second-order jet (u, u_x0, u_x0x0)
// via mma.sync bf16 3-term split GEMMs (hh + hl + lh), fully fused per 32 samples.
// R7: weights pre-split into bf16 hi/lo plane images by a prep kernel; the hot
// kernel stages them with plain uint4 copies (no per-block fp32->bf16 conversion).

#define HID  256
#define RS   132        // H row stride in 8B {hi,lo} pairs  (132 mod 16 == 4)
#define BSN  264        // W plane row stride in 4B words    (264 mod 32 == 8)
#define BPLW (32*BSN)   // words per W plane (one K-chunk of 64)

// SMEM byte offsets
#define SM_H    0
#define SM_B    101376                  // H = 96 rows * 132 pairs * 8B
#define SM_BIAS (SM_B + 2*BPLW*4)       // 101376 + 67584 = 168960
#define SM_W4   (SM_BIAS + 2048)        // 171008
#define SM_X    (SM_W4 + 1024)          // 172032
#define SM_OUT  (SM_X + 256)            // 172288
#define SM_TOT  (SM_OUT + 384)          // 172672

// pre-split weight plane images: [layer][kc][plane hi/lo][BPLW words]
__device__ __align__(16) uint32_t g_W[2][4][2][BPLW];

__device__ __forceinline__ void tanh_d(float x, float& a, float& s2) {
    x = fminf(fmaxf(x, -15.f), 15.f);
    float t = exp2f(x * 2.8853900817779268f);
    float d = 1.f + t, r;
    asm("rcp.approx.ftz.f32 %0, %1;" : "=f"(r) : "f"(d));
    r = r * (2.f - d * r);
    a  = 1.f - 2.f * r;
    s2 = 4.f * r * (1.f - r);
}

// pack (x,y) -> hi word {bf16(x),bf16(y)} and lo word of residuals
__device__ __forceinline__ void pk2(float x, float y, uint32_t& hi, uint32_t& lo) {
    __nv_bfloat16 hx = __float2bfloat16_rn(x);
    __nv_bfloat16 hy = __float2bfloat16_rn(y);
    __nv_bfloat16 lx = __float2bfloat16_rn(x - __bfloat162float(hx));
    __nv_bfloat16 ly = __float2bfloat16_rn(y - __bfloat162float(hy));
    hi = (uint32_t)__bfloat16_as_ushort(hx) | ((uint32_t)__bfloat16_as_ushort(hy) << 16);
    lo = (uint32_t)__bfloat16_as_ushort(lx) | ((uint32_t)__bfloat16_as_ushort(ly) << 16);
}

#define MMA(Dx, A, Bp)                                                          \
    asm volatile("mma.sync.aligned.m16n8k16.row.col.f32.bf16.bf16.f32 "         \
                 "{%0,%1,%2,%3},{%4,%5,%6,%7},{%8,%9},{%0,%1,%2,%3};"           \
                 : "+f"((Dx)[0]), "+f"((Dx)[1]), "+f"((Dx)[2]), "+f"((Dx)[3])   \
                 : "r"((A)[0]), "r"((A)[1]), "r"((A)[2]), "r"((A)[3]),          \
                   "r"((Bp)[0]), "r"((Bp)[1]))

// ---- prep: split W2/W3 -> plane images (same layout the old staging built) ----
extern "C" __global__ void prep_w(const float* __restrict__ W2,
                                  const float* __restrict__ W3) {
    const int l = blockIdx.x >> 2, kc = blockIdx.x & 3, t = threadIdx.x;
    const float* W = l ? W3 : W2;
    uint32_t* hi = g_W[l][kc][0];
    uint32_t* lo = g_W[l][kc][1];
    #pragma unroll 4
    for (int e = 0; e < 32; ++e) {
        int idx = e * 256 + t;
        int kp = idx >> 8, n = idx & 255;
        float v0 = W[(kc * 64 + 2 * kp) * HID + n];
        float v1 = W[(kc * 64 + 2 * kp + 1) * HID + n];
        uint32_t h, lw;
        pk2(v0, v1, h, lw);
        hi[kp * BSN + n] = h;
        lo[kp * BSN + n] = lw;
    }
}

extern "C" __global__ void __launch_bounds__(256, 1)
pinn_mma_kernel(const float* __restrict__ x,
                const float* __restrict__ W1, const float* __restrict__ b1,
                const float* __restrict__ b2, const float* __restrict__ b3,
                const float* __restrict__ W4, const float* __restrict__ b4,
                float* __restrict__ out, int B) {
    extern __shared__ unsigned char smem[];
    uint2*    Hb     = (uint2*)(smem + SM_H);          // {hi,lo} pairs
    uint32_t* Whi    = (uint32_t*)(smem + SM_B);
    uint32_t* Wlo    = Whi + BPLW;
    float*    biasSm = (float*)(smem + SM_BIAS);        // [2][256]
    float*    w4Sm   = (float*)(smem + SM_W4);
    float2*   xSm    = (float2*)(smem + SM_X);
    float*    outSm  = (float*)(smem + SM_OUT);         // [3][32]

    const int t = threadIdx.x, lane = t & 31, w = t >> 5;
    const int bs = blockIdx.x * 32;

    if (t < 96) outSm[t] = 0.f;
    if (t < 32) xSm[t] = ((const float2*)x)[bs + t];
    biasSm[t]       = b2[t];
    biasSm[256 + t] = b3[t];
    w4Sm[t] = W4[t];
    __syncthreads();

    // ---- layer 1: jets into H (z' = W1[0][u], z'' = 0) ----
    {
        const int up = t & 127, sh = t >> 7;        // unit pair, sample half
        float2 c0 = ((const float2*)W1)[up];        // W1[0][u0], W1[0][u1]
        float2 c1 = ((const float2*)(W1 + HID))[up];
        float2 bb = ((const float2*)b1)[up];
        #pragma unroll 4
        for (int i = 0; i < 16; ++i) {
            int s = sh * 16 + i;
            float2 xv = xSm[s];
            float a0, s20, a1u0, a2u0, a0b, s21, a1u1, a2u1;
            tanh_d(fmaf(xv.x, c0.x, fmaf(xv.y, c1.x, bb.x)), a0, s20);
            tanh_d(fmaf(xv.x, c0.y, fmaf(xv.y, c1.y, bb.y)), a0b, s21);
            a1u0 = s20 * c0.x;  a2u0 = -2.f * a0  * a1u0 * c0.x;
            a1u1 = s21 * c0.y;  a2u1 = -2.f * a0b * a1u1 * c0.y;
            uint32_t h, lo2;
            pk2(a0, a0b, h, lo2);   Hb[(0 * 32 + s) * RS + up] = make_uint2(h, lo2);
            pk2(a1u0, a1u1, h, lo2);Hb[(1 * 32 + s) * RS + up] = make_uint2(h, lo2);
            pk2(a2u0, a2u1, h, lo2);Hb[(2 * 32 + s) * RS + up] = make_uint2(h, lo2);
        }
    }

    float D[3][2][4][4];
    float ps[2][2][3];   // last-layer partials [mt][rowhalf][stream]

    #pragma unroll 1
    for (int l = 0; l < 2; ++l) {
        #pragma unroll
        for (int a = 0; a < 3; ++a)
            #pragma unroll
            for (int b_ = 0; b_ < 2; ++b_)
                #pragma unroll
                for (int c = 0; c < 4; ++c)
                    #pragma unroll
                    for (int d = 0; d < 4; ++d) D[a][b_][c][d] = 0.f;

        #pragma unroll 1
        for (int kc = 0; kc < 4; ++kc) {
            __syncthreads();
            // stage pre-split planes (hi+lo contiguous: 2*BPLW words = 4224 uint4)
            {
                const uint4* src = (const uint4*)g_W[l][kc][0];
                uint4* dst = (uint4*)Whi;
                #pragma unroll
                for (int i = 0; i < 17; ++i) {
                    int idx = t + (i << 8);
                    if (idx < 2 * BPLW / 4) dst[idx] = src[idx];
                }
            }
            __syncthreads();

            #pragma unroll
            for (int ks = 0; ks < 4; ++ks) {
                const int kpl = ks * 8 + (lane & 3);
                uint32_t Bh[4][2], Bl[4][2];
                #pragma unroll
                for (int nt = 0; nt < 4; ++nt) {
                    int n = (w << 5) + (nt << 3) + (lane >> 2);
                    Bh[nt][0] = Whi[kpl * BSN + n];
                    Bh[nt][1] = Whi[(kpl + 4) * BSN + n];
                    Bl[nt][0] = Wlo[kpl * BSN + n];
                    Bl[nt][1] = Wlo[(kpl + 4) * BSN + n];
                }
                const int kp = (kc * 4 + ks) * 8 + (lane & 3);
                #pragma unroll
                for (int mt = 0; mt < 2; ++mt) {
                    const int row0 = (mt << 4) + (lane >> 2);
                    #pragma unroll
                    for (int st = 0; st < 3; ++st) {
                        int base = (st * 32 + row0) * RS + kp;
                        uint2 p00 = Hb[base];
                        uint2 p10 = Hb[base + 8 * RS];
                        uint2 p01 = Hb[base + 4];
                        uint2 p11 = Hb[base + 8 * RS + 4];
                        uint32_t Ah[4] = {p00.x, p10.x, p01.x, p11.x};
                        uint32_t Al[4] = {p00.y, p10.y, p01.y, p11.y};
                        #pragma unroll
                        for (int nt = 0; nt < 4; ++nt) {
                            MMA(D[st][mt][nt], Ah, Bh[nt]);
                            MMA(D[st][mt][nt], Ah, Bl[nt]);
                            MMA(D[st][mt][nt], Al, Bh[nt]);
                        }
                    }
                }
            }
        }
        __syncthreads();   // everyone done reading H/W before epilogue rewrites H

        // ---- jet epilogue ----
        if (l == 1) {
            #pragma unroll
            for (int a = 0; a < 2; ++a)
                #pragma unroll
                for (int b_ = 0; b_ < 2; ++b_)
                    #pragma unroll
                    for (int c = 0; c < 3; ++c) ps[a][b_][c] = 0.f;
        }
        #pragma unroll
        for (int mt = 0; mt < 2; ++mt) {
            #pragma unroll
            for (int nt = 0; nt < 4; ++nt) {
                const int u0 = (w << 5) + (nt << 3) + ((lane & 3) << 1);
                float2 bb = *(const float2*)(biasSm + (l ? 256 : 0) + u0);
                float2 w4v = *(const float2*)(w4Sm + u0);
                float av[4], a1v[4], a2v[4];
                #pragma unroll
                for (int p = 0; p < 4; ++p) {
                    float z  = D[0][mt][nt][p] + ((p & 1) ? bb.y : bb.x);
                    float z1 = D[1][mt][nt][p];
                    float z2 = D[2][mt][nt][p];
                    float a, s2;
                    tanh_d(z, a, s2);
                    av[p]  = a;
                    a1v[p] = s2 * z1;
                    a2v[p] = s2 * z2 - 2.f * a * a1v[p] * z1;
                }
                if (l == 0) {
                    const int r0 = (mt << 4) + (lane >> 2);
                    const int pi = (w << 4) + (nt << 2) + (lane & 3);
                    uint32_t h, lo2;
                    pk2(av[0],  av[1],  h, lo2); Hb[(0*32 + r0    ) * RS + pi] = make_uint2(h, lo2);
                    pk2(av[2],  av[3],  h, lo2); Hb[(0*32 + r0 + 8) * RS + pi] = make_uint2(h, lo2);
                    pk2(a1v[0], a1v[1], h, lo2); Hb[(1*32 + r0    ) * RS + pi] = make_uint2(h, lo2);
                    pk2(a1v[2], a1v[3], h, lo2); Hb[(1*32 + r0 + 8) * RS + pi] = make_uint2(h, lo2);
                    pk2(a2v[0], a2v[1], h, lo2); Hb[(2*32 + r0    ) * RS + pi] = make_uint2(h, lo2);
                    pk2(a2v[2], a2v[3], h, lo2); Hb[(2*32 + r0 + 8) * RS + pi] = make_uint2(h, lo2);
                } else {
                    #pragma unroll
                    for (int p = 0; p < 4; ++p) {
                        float wv = (p & 1) ? w4v.y : w4v.x;
                        int rh = p >> 1;
                        ps[mt][rh][0] += av[p]  * wv;
                        ps[mt][rh][1] += a1v[p] * wv;
                        ps[mt][rh][2] += a2v[p] * wv;
                    }
                }
            }
        }
        if (l == 1) {
            #pragma unroll
            for (int mt = 0; mt < 2; ++mt)
                #pragma unroll
                for (int rh = 0; rh < 2; ++rh)
                    #pragma unroll
                    for (int st = 0; st < 3; ++st) {
                        float v = ps[mt][rh][st];
                        v += __shfl_xor_sync(0xffffffffu, v, 1);
                        v += __shfl_xor_sync(0xffffffffu, v, 2);
                        if ((lane & 3) == 0)
                            atomicAdd(&outSm[st * 32 + mt * 16 + (lane >> 2) + rh * 8], v);
                    }
        }
    }

    __syncthreads();
    if (t < 96) {
        int st = t >> 5, s = t & 31;
        float v = outSm[t] + (st == 0 ? b4[0] : 0.f);
        out[st * B + bs + s] = v;
    }
}

extern "C" void kernel_launch(void* const* d_in, const int* in_sizes, int n_in,
                              void* d_out, int out_size) {
    const float* x  = (const float*)d_in[0];
    const float* W1 = (const float*)d_in[1];
    const float* b1 = (const float*)d_in[2];
    const float* W2 = (const float*)d_in[3];
    const float* b2 = (const float*)d_in[4];
    const float* W3 = (const float*)d_in[5];
    const float* b3 = (const float*)d_in[6];
    const float* W4 = (const float*)d_in[7];
    const float* b4 = (const float*)d_in[8];
    float* out = (float*)d_out;
    const int B = in_sizes[0] / 2;

    prep_w<<<8, 256>>>(W2, W3);

    cudaFuncSetAttribute(pinn_mma_kernel,
                         cudaFuncAttributeMaxDynamicSharedMemorySize, SM_TOT);
    pinn_mma_kernel<<<B / 32, 256, SM_TOT>>>(x, W1, b1, b2, b3, W4, b4, out, B);
}

// round 8
// speedup vs baseline: 2.7614x; 1.1013x over previous
#include <cuda_runtime.h>
#include <cuda_bf16.h>
#include <cstdint>

// GradientLayerPoisson: tanh-MLP 2->256->256->256->1 second-order jet
// via mma.sync bf16 3-term split GEMMs (hh + hl + lh), fully fused.
// R8: 16 samples/CTA, 2 CTAs/SM; B fragments loaded directly from a
// fragment-ordered pre-split weight image in global (L2-resident),
// software-pipelined one k-step ahead. No W staging in SMEM.

#define HID  256
#define RS   132        // H row stride in 8B {hi,lo} pairs (132 mod 16 == 4)

// SMEM byte offsets (48 H rows * 132 pairs * 8B = 50688)
#define SM_H    0
#define SM_BIAS 50688   // [2][256] fp32
#define SM_W4   52736   // [256] fp32
#define SM_X    53760   // [16] float2
#define SM_OUT  53888   // [3][16] fp32
#define SM_TOT  54080

// fragment-ordered weight image: [l][kc][ks][warp][lane][16 words]
//  words 0-3 : Bh[nt][0], 4-7: Bh[nt][1], 8-11: Bl[nt][0], 12-15: Bl[nt][1]
__device__ __align__(16) uint32_t g_Wp[2][4][4][8][32][16];

__device__ __forceinline__ void tanh_d(float x, float& a, float& s2) {
    x = fminf(fmaxf(x, -15.f), 15.f);
    float t = exp2f(x * 2.8853900817779268f);
    float d = 1.f + t, r;
    asm("rcp.approx.ftz.f32 %0, %1;" : "=f"(r) : "f"(d));
    r = r * (2.f - d * r);
    a  = 1.f - 2.f * r;
    s2 = 4.f * r * (1.f - r);
}

__device__ __forceinline__ void pk2(float x, float y, uint32_t& hi, uint32_t& lo) {
    __nv_bfloat16 hx = __float2bfloat16_rn(x);
    __nv_bfloat16 hy = __float2bfloat16_rn(y);
    __nv_bfloat16 lx = __float2bfloat16_rn(x - __bfloat162float(hx));
    __nv_bfloat16 ly = __float2bfloat16_rn(y - __bfloat162float(hy));
    hi = (uint32_t)__bfloat16_as_ushort(hx) | ((uint32_t)__bfloat16_as_ushort(hy) << 16);
    lo = (uint32_t)__bfloat16_as_ushort(lx) | ((uint32_t)__bfloat16_as_ushort(ly) << 16);
}

#define MMA(Dx, A, B0, B1)                                                      \
    asm volatile("mma.sync.aligned.m16n8k16.row.col.f32.bf16.bf16.f32 "         \
                 "{%0,%1,%2,%3},{%4,%5,%6,%7},{%8,%9},{%0,%1,%2,%3};"           \
                 : "+f"((Dx)[0]), "+f"((Dx)[1]), "+f"((Dx)[2]), "+f"((Dx)[3])   \
                 : "r"((A)[0]), "r"((A)[1]), "r"((A)[2]), "r"((A)[3]),          \
                   "r"(B0), "r"(B1))

// ---- prep: bake W2/W3 into fragment-ordered hi/lo image ----
extern "C" __global__ void prep_w(const float* __restrict__ W2,
                                  const float* __restrict__ W3) {
    const int b = blockIdx.x;                 // 32 blocks: l(2) x kc(4) x ks(4)
    const int l = b >> 4, kc = (b >> 2) & 3, ks = b & 3;
    const int t = threadIdx.x, w = t >> 5, lane = t & 31;
    const float* W = l ? W3 : W2;
    uint32_t* dst = g_Wp[l][kc][ks][w][lane];
    #pragma unroll
    for (int j = 0; j < 2; ++j)
        #pragma unroll
        for (int nt = 0; nt < 4; ++nt) {
            int kp = ks * 8 + (lane & 3) + 4 * j;
            int n  = w * 32 + nt * 8 + (lane >> 2);
            float v0 = W[(kc * 64 + 2 * kp) * HID + n];
            float v1 = W[(kc * 64 + 2 * kp + 1) * HID + n];
            uint32_t h, lo;
            pk2(v0, v1, h, lo);
            dst[nt + 4 * j]     = h;
            dst[8 + nt + 4 * j] = lo;
        }
}

extern "C" __global__ void __launch_bounds__(256, 2)
pinn_mma_kernel(const float* __restrict__ x,
                const float* __restrict__ W1, const float* __restrict__ b1,
                const float* __restrict__ b2, const float* __restrict__ b3,
                const float* __restrict__ W4, const float* __restrict__ b4,
                float* __restrict__ out, int B) {
    extern __shared__ unsigned char smem[];
    uint2*  Hb     = (uint2*)(smem + SM_H);
    float*  biasSm = (float*)(smem + SM_BIAS);
    float*  w4Sm   = (float*)(smem + SM_W4);
    float2* xSm    = (float2*)(smem + SM_X);
    float*  outSm  = (float*)(smem + SM_OUT);

    const int t = threadIdx.x, lane = t & 31, w = t >> 5;
    const int bs = blockIdx.x * 16;

    if (t < 48) outSm[t] = 0.f;
    if (t < 16) xSm[t] = ((const float2*)x)[bs + t];
    biasSm[t]       = b2[t];
    biasSm[256 + t] = b3[t];
    w4Sm[t] = W4[t];
    __syncthreads();

    // ---- layer 1: jets into H (z' = W1[0][u], z'' = 0) ----
    {
        const int up = t & 127, sh = t >> 7;
        float2 c0 = ((const float2*)W1)[up];
        float2 c1 = ((const float2*)(W1 + HID))[up];
        float2 bb = ((const float2*)b1)[up];
        #pragma unroll 4
        for (int i = 0; i < 8; ++i) {
            int s = sh * 8 + i;
            float2 xv = xSm[s];
            float a0, s20, a0b, s21;
            tanh_d(fmaf(xv.x, c0.x, fmaf(xv.y, c1.x, bb.x)), a0, s20);
            tanh_d(fmaf(xv.x, c0.y, fmaf(xv.y, c1.y, bb.y)), a0b, s21);
            float a1u0 = s20 * c0.x, a2u0 = -2.f * a0  * a1u0 * c0.x;
            float a1u1 = s21 * c0.y, a2u1 = -2.f * a0b * a1u1 * c0.y;
            uint32_t h, lo2;
            pk2(a0, a0b, h, lo2);    Hb[(0 * 16 + s) * RS + up] = make_uint2(h, lo2);
            pk2(a1u0, a1u1, h, lo2); Hb[(1 * 16 + s) * RS + up] = make_uint2(h, lo2);
            pk2(a2u0, a2u1, h, lo2); Hb[(2 * 16 + s) * RS + up] = make_uint2(h, lo2);
        }
    }
    __syncthreads();

    float D[3][4][4];
    float ps[2][3];

    #pragma unroll 1
    for (int l = 0; l < 2; ++l) {
        #pragma unroll
        for (int a = 0; a < 3; ++a)
            #pragma unroll
            for (int c = 0; c < 4; ++c)
                #pragma unroll
                for (int d = 0; d < 4; ++d) D[a][c][d] = 0.f;

        const uint4* wp = (const uint4*)g_Wp[l];
        // uint4 index for step: ((step*8 + w)*32 + lane)*4
        uint32_t q[16];
        {
            const uint4* src = wp + (((0 * 8 + w) * 32 + lane) << 2);
            *(uint4*)(q + 0)  = src[0];
            *(uint4*)(q + 4)  = src[1];
            *(uint4*)(q + 8)  = src[2];
            *(uint4*)(q + 12) = src[3];
        }

        #pragma unroll 4
        for (int step = 0; step < 16; ++step) {
            uint32_t p[16];
            {
                int ns = (step + 1) & 15;
                const uint4* src = wp + (((ns * 8 + w) * 32 + lane) << 2);
                *(uint4*)(p + 0)  = src[0];
                *(uint4*)(p + 4)  = src[1];
                *(uint4*)(p + 8)  = src[2];
                *(uint4*)(p + 12) = src[3];
            }
            const int kp = step * 8 + (lane & 3);
            #pragma unroll
            for (int st = 0; st < 3; ++st) {
                int base = (st * 16 + (lane >> 2)) * RS + kp;
                uint2 p00 = Hb[base];
                uint2 p10 = Hb[base + 8 * RS];
                uint2 p01 = Hb[base + 4];
                uint2 p11 = Hb[base + 8 * RS + 4];
                uint32_t Ah[4] = {p00.x, p10.x, p01.x, p11.x};
                uint32_t Al[4] = {p00.y, p10.y, p01.y, p11.y};
                #pragma unroll
                for (int nt = 0; nt < 4; ++nt) {
                    MMA(D[st][nt], Ah, q[nt], q[4 + nt]);
                    MMA(D[st][nt], Ah, q[8 + nt], q[12 + nt]);
                    MMA(D[st][nt], Al, q[nt], q[4 + nt]);
                }
            }
            #pragma unroll
            for (int i = 0; i < 16; ++i) q[i] = p[i];
        }
        __syncthreads();   // all warps done reading H before epilogue rewrites it

        // ---- jet epilogue ----
        if (l == 1) {
            #pragma unroll
            for (int a = 0; a < 2; ++a)
                #pragma unroll
                for (int c = 0; c < 3; ++c) ps[a][c] = 0.f;
        }
        #pragma unroll
        for (int nt = 0; nt < 4; ++nt) {
            const int u0 = (w << 5) + (nt << 3) + ((lane & 3) << 1);
            float2 bb  = *(const float2*)(biasSm + (l ? 256 : 0) + u0);
            float2 w4v = *(const float2*)(w4Sm + u0);
            float av[4], a1v[4], a2v[4];
            #pragma unroll
            for (int p_ = 0; p_ < 4; ++p_) {
                float z  = D[0][nt][p_] + ((p_ & 1) ? bb.y : bb.x);
                float z1 = D[1][nt][p_];
                float z2 = D[2][nt][p_];
                float a, s2;
                tanh_d(z, a, s2);
                av[p_]  = a;
                a1v[p_] = s2 * z1;
                a2v[p_] = s2 * z2 - 2.f * a * a1v[p_] * z1;
            }
            if (l == 0) {
                const int r0 = lane >> 2;
                const int pi = (w << 4) + (nt << 2) + (lane & 3);
                uint32_t h, lo2;
                pk2(av[0],  av[1],  h, lo2); Hb[(0*16 + r0    ) * RS + pi] = make_uint2(h, lo2);
                pk2(av[2],  av[3],  h, lo2); Hb[(0*16 + r0 + 8) * RS + pi] = make_uint2(h, lo2);
                pk2(a1v[0], a1v[1], h, lo2); Hb[(1*16 + r0    ) * RS + pi] = make_uint2(h, lo2);
                pk2(a1v[2], a1v[3], h, lo2); Hb[(1*16 + r0 + 8) * RS + pi] = make_uint2(h, lo2);
                pk2(a2v[0], a2v[1], h, lo2); Hb[(2*16 + r0    ) * RS + pi] = make_uint2(h, lo2);
                pk2(a2v[2], a2v[3], h, lo2); Hb[(2*16 + r0 + 8) * RS + pi] = make_uint2(h, lo2);
            } else {
                #pragma unroll
                for (int p_ = 0; p_ < 4; ++p_) {
                    float wv = (p_ & 1) ? w4v.y : w4v.x;
                    int rh = p_ >> 1;
                    ps[rh][0] += av[p_]  * wv;
                    ps[rh][1] += a1v[p_] * wv;
                    ps[rh][2] += a2v[p_] * wv;
                }
            }
        }
        if (l == 0) {
            __syncthreads();           // H fully rewritten before layer-2 MMAs
        } else {
            #pragma unroll
            for (int rh = 0; rh < 2; ++rh)
                #pragma unroll
                for (int st = 0; st < 3; ++st) {
                    float v = ps[rh][st];
                    v += __shfl_xor_sync(0xffffffffu, v, 1);
                    v += __shfl_xor_sync(0xffffffffu, v, 2);
                    if ((lane & 3) == 0)
                        atomicAdd(&outSm[st * 16 + (lane >> 2) + rh * 8], v);
                }
        }
    }

    __syncthreads();
    if (t < 48) {
        int st = t >> 4, s = t & 15;
        float v = outSm[t] + (st == 0 ? b4[0] : 0.f);
        out[st * B + bs + s] = v;
    }
}

extern "C" void kernel_launch(void* const* d_in, const int* in_sizes, int n_in,
                              void* d_out, int out_size) {
    const float* x  = (const float*)d_in[0];
    const float* W1 = (const float*)d_in[1];
    const float* b1 = (const float*)d_in[2];
    const float* W2 = (const float*)d_in[3];
    const float* b2 = (const float*)d_in[4];
    const float* W3 = (const float*)d_in[5];
    const float* b3 = (const float*)d_in[6];
    const float* W4 = (const float*)d_in[7];
    const float* b4 = (const float*)d_in[8];
    float* out = (float*)d_out;
    const int B = in_sizes[0] / 2;

    prep_w<<<32, 256>>>(W2, W3);

    cudaFuncSetAttribute(pinn_mma_kernel,
                         cudaFuncAttributeMaxDynamicSharedMemorySize, SM_TOT);
    pinn_mma_kernel<<<B / 16, 256, SM_TOT>>>(x, W1, b1, b2, b3, W4, b4, out, B);
}

// round 9
// speedup vs baseline: 2.8995x; 1.0500x over previous
#include <cuda_runtime.h>
#include <cuda_bf16.h>
#include <cstdint>

// GradientLayerPoisson: tanh-MLP 2->256->256->256->1 second-order jet
// via mma.sync bf16 3-term split GEMMs (hh + hl + lh), fully fused.
// R9: fully-unrolled k-loop with parity double-buffer prefetch (no register
// copies, constant-folded addresses). 16 samples/CTA, 2 CTAs/SM.

#define HID  256
#define RS   132        // H row stride in 8B {hi,lo} pairs (132 mod 16 == 4)

// SMEM byte offsets (48 H rows * 132 pairs * 8B = 50688)
#define SM_H    0
#define SM_BIAS 50688   // [2][256] fp32
#define SM_W4   52736   // [256] fp32
#define SM_X    53760   // [16] float2
#define SM_OUT  53888   // [3][16] fp32
#define SM_TOT  54080

// fragment-ordered weight image: [l][kc][ks][warp][lane][16 words]
//  words 0-3 : Bh[nt][0], 4-7: Bh[nt][1], 8-11: Bl[nt][0], 12-15: Bl[nt][1]
__device__ __align__(16) uint32_t g_Wp[2][4][4][8][32][16];

__device__ __forceinline__ void tanh_d(float x, float& a, float& s2) {
    x = fminf(fmaxf(x, -15.f), 15.f);
    float t = exp2f(x * 2.8853900817779268f);
    float d = 1.f + t, r;
    asm("rcp.approx.ftz.f32 %0, %1;" : "=f"(r) : "f"(d));
    r = r * (2.f - d * r);
    a  = 1.f - 2.f * r;
    s2 = 4.f * r * (1.f - r);
}

__device__ __forceinline__ void pk2(float x, float y, uint32_t& hi, uint32_t& lo) {
    __nv_bfloat16 hx = __float2bfloat16_rn(x);
    __nv_bfloat16 hy = __float2bfloat16_rn(y);
    __nv_bfloat16 lx = __float2bfloat16_rn(x - __bfloat162float(hx));
    __nv_bfloat16 ly = __float2bfloat16_rn(y - __bfloat162float(hy));
    hi = (uint32_t)__bfloat16_as_ushort(hx) | ((uint32_t)__bfloat16_as_ushort(hy) << 16);
    lo = (uint32_t)__bfloat16_as_ushort(lx) | ((uint32_t)__bfloat16_as_ushort(ly) << 16);
}

#define MMA(Dx, A, B0, B1)                                                      \
    asm volatile("mma.sync.aligned.m16n8k16.row.col.f32.bf16.bf16.f32 "         \
                 "{%0,%1,%2,%3},{%4,%5,%6,%7},{%8,%9},{%0,%1,%2,%3};"           \
                 : "+f"((Dx)[0]), "+f"((Dx)[1]), "+f"((Dx)[2]), "+f"((Dx)[3])   \
                 : "r"((A)[0]), "r"((A)[1]), "r"((A)[2]), "r"((A)[3]),          \
                   "r"(B0), "r"(B1))

// ---- prep: bake W2/W3 into fragment-ordered hi/lo image ----
extern "C" __global__ void prep_w(const float* __restrict__ W2,
                                  const float* __restrict__ W3) {
    const int b = blockIdx.x;                 // 32 blocks: l(2) x kc(4) x ks(4)
    const int l = b >> 4, kc = (b >> 2) & 3, ks = b & 3;
    const int t = threadIdx.x, w = t >> 5, lane = t & 31;
    const float* W = l ? W3 : W2;
    uint32_t* dst = g_Wp[l][kc][ks][w][lane];
    #pragma unroll
    for (int j = 0; j < 2; ++j)
        #pragma unroll
        for (int nt = 0; nt < 4; ++nt) {
            int kp = ks * 8 + (lane & 3) + 4 * j;
            int n  = w * 32 + nt * 8 + (lane >> 2);
            float v0 = W[(kc * 64 + 2 * kp) * HID + n];
            float v1 = W[(kc * 64 + 2 * kp + 1) * HID + n];
            uint32_t h, lo;
            pk2(v0, v1, h, lo);
            dst[nt + 4 * j]     = h;
            dst[8 + nt + 4 * j] = lo;
        }
}

extern "C" __global__ void __launch_bounds__(256, 2)
pinn_mma_kernel(const float* __restrict__ x,
                const float* __restrict__ W1, const float* __restrict__ b1,
                const float* __restrict__ b2, const float* __restrict__ b3,
                const float* __restrict__ W4, const float* __restrict__ b4,
                float* __restrict__ out, int B) {
    extern __shared__ unsigned char smem[];
    uint2*  Hb     = (uint2*)(smem + SM_H);
    float*  biasSm = (float*)(smem + SM_BIAS);
    float*  w4Sm   = (float*)(smem + SM_W4);
    float2* xSm    = (float2*)(smem + SM_X);
    float*  outSm  = (float*)(smem + SM_OUT);

    const int t = threadIdx.x, lane = t & 31, w = t >> 5;
    const int bs = blockIdx.x * 16;

    if (t < 48) outSm[t] = 0.f;
    if (t < 16) xSm[t] = ((const float2*)x)[bs + t];
    biasSm[t]       = b2[t];
    biasSm[256 + t] = b3[t];
    w4Sm[t] = W4[t];
    __syncthreads();

    // ---- layer 1: jets into H (z' = W1[0][u], z'' = 0) ----
    {
        const int up = t & 127, sh = t >> 7;
        float2 c0 = ((const float2*)W1)[up];
        float2 c1 = ((const float2*)(W1 + HID))[up];
        float2 bb = ((const float2*)b1)[up];
        #pragma unroll 4
        for (int i = 0; i < 8; ++i) {
            int s = sh * 8 + i;
            float2 xv = xSm[s];
            float a0, s20, a0b, s21;
            tanh_d(fmaf(xv.x, c0.x, fmaf(xv.y, c1.x, bb.x)), a0, s20);
            tanh_d(fmaf(xv.x, c0.y, fmaf(xv.y, c1.y, bb.y)), a0b, s21);
            float a1u0 = s20 * c0.x, a2u0 = -2.f * a0  * a1u0 * c0.x;
            float a1u1 = s21 * c0.y, a2u1 = -2.f * a0b * a1u1 * c0.y;
            uint32_t h, lo2;
            pk2(a0, a0b, h, lo2);    Hb[(0 * 16 + s) * RS + up] = make_uint2(h, lo2);
            pk2(a1u0, a1u1, h, lo2); Hb[(1 * 16 + s) * RS + up] = make_uint2(h, lo2);
            pk2(a2u0, a2u1, h, lo2); Hb[(2 * 16 + s) * RS + up] = make_uint2(h, lo2);
        }
    }
    __syncthreads();

    float D[3][4][4];
    float ps[2][3];

    // per-thread invariant pieces
    const int g4 = lane >> 2, tid3 = lane & 3;
    const uint2* HbT = Hb + g4 * RS + tid3;     // + st*16*RS + step*8 (+4 / +8*RS)

    #pragma unroll 1
    for (int l = 0; l < 2; ++l) {
        #pragma unroll
        for (int a = 0; a < 3; ++a)
            #pragma unroll
            for (int c = 0; c < 4; ++c)
                #pragma unroll
                for (int d = 0; d < 4; ++d) D[a][c][d] = 0.f;

        const uint4* wpT = (const uint4*)g_Wp[l] + ((w * 32 + lane) << 2); // + step*1024
        uint32_t q[2][16];
        *(uint4*)(q[0] + 0)  = wpT[0];
        *(uint4*)(q[0] + 4)  = wpT[1];
        *(uint4*)(q[0] + 8)  = wpT[2];
        *(uint4*)(q[0] + 12) = wpT[3];

        #pragma unroll
        for (int step = 0; step < 16; ++step) {
            const int cur = step & 1, nxt = cur ^ 1;
            if (step < 15) {
                const uint4* src = wpT + ((step + 1) << 10);
                *(uint4*)(q[nxt] + 0)  = src[0];
                *(uint4*)(q[nxt] + 4)  = src[1];
                *(uint4*)(q[nxt] + 8)  = src[2];
                *(uint4*)(q[nxt] + 12) = src[3];
            }
            #pragma unroll
            for (int st = 0; st < 3; ++st) {
                const uint2* hp = HbT + st * (16 * RS) + step * 8;
                uint2 p00 = hp[0];
                uint2 p10 = hp[8 * RS];
                uint2 p01 = hp[4];
                uint2 p11 = hp[8 * RS + 4];
                uint32_t Ah[4] = {p00.x, p10.x, p01.x, p11.x};
                uint32_t Al[4] = {p00.y, p10.y, p01.y, p11.y};
                #pragma unroll
                for (int nt = 0; nt < 4; ++nt) {
                    MMA(D[st][nt], Ah, q[cur][nt], q[cur][4 + nt]);
                    MMA(D[st][nt], Ah, q[cur][8 + nt], q[cur][12 + nt]);
                    MMA(D[st][nt], Al, q[cur][nt], q[cur][4 + nt]);
                }
            }
        }
        __syncthreads();   // all warps done reading H before epilogue rewrites it

        // ---- jet epilogue ----
        if (l == 1) {
            #pragma unroll
            for (int a = 0; a < 2; ++a)
                #pragma unroll
                for (int c = 0; c < 3; ++c) ps[a][c] = 0.f;
        }
        #pragma unroll
        for (int nt = 0; nt < 4; ++nt) {
            const int u0 = (w << 5) + (nt << 3) + (tid3 << 1);
            float2 bb  = *(const float2*)(biasSm + (l ? 256 : 0) + u0);
            float2 w4v = *(const float2*)(w4Sm + u0);
            float av[4], a1v[4], a2v[4];
            #pragma unroll
            for (int p_ = 0; p_ < 4; ++p_) {
                float z  = D[0][nt][p_] + ((p_ & 1) ? bb.y : bb.x);
                float z1 = D[1][nt][p_];
                float z2 = D[2][nt][p_];
                float a, s2;
                tanh_d(z, a, s2);
                av[p_]  = a;
                a1v[p_] = s2 * z1;
                a2v[p_] = s2 * z2 - 2.f * a * a1v[p_] * z1;
            }
            if (l == 0) {
                const int pi = (w << 4) + (nt << 2) + tid3;
                uint32_t h, lo2;
                pk2(av[0],  av[1],  h, lo2); Hb[(0*16 + g4    ) * RS + pi] = make_uint2(h, lo2);
                pk2(av[2],  av[3],  h, lo2); Hb[(0*16 + g4 + 8) * RS + pi] = make_uint2(h, lo2);
                pk2(a1v[0], a1v[1], h, lo2); Hb[(1*16 + g4    ) * RS + pi] = make_uint2(h, lo2);
                pk2(a1v[2], a1v[3], h, lo2); Hb[(1*16 + g4 + 8) * RS + pi] = make_uint2(h, lo2);
                pk2(a2v[0], a2v[1], h, lo2); Hb[(2*16 + g4    ) * RS + pi] = make_uint2(h, lo2);
                pk2(a2v[2], a2v[3], h, lo2); Hb[(2*16 + g4 + 8) * RS + pi] = make_uint2(h, lo2);
            } else {
                #pragma unroll
                for (int p_ = 0; p_ < 4; ++p_) {
                    float wv = (p_ & 1) ? w4v.y : w4v.x;
                    int rh = p_ >> 1;
                    ps[rh][0] += av[p_]  * wv;
                    ps[rh][1] += a1v[p_] * wv;
                    ps[rh][2] += a2v[p_] * wv;
                }
            }
        }
        if (l == 0) {
            __syncthreads();           // H fully rewritten before layer-2 MMAs
        } else {
            #pragma unroll
            for (int rh = 0; rh < 2; ++rh)
                #pragma unroll
                for (int st = 0; st < 3; ++st) {
                    float v = ps[rh][st];
                    v += __shfl_xor_sync(0xffffffffu, v, 1);
                    v += __shfl_xor_sync(0xffffffffu, v, 2);
                    if (tid3 == 0)
                        atomicAdd(&outSm[st * 16 + g4 + rh * 8], v);
                }
        }
    }

    __syncthreads();
    if (t < 48) {
        int st = t >> 4, s = t & 15;
        float v = outSm[t] + (st == 0 ? b4[0] : 0.f);
        out[st * B + bs + s] = v;
    }
}

extern "C" void kernel_launch(void* const* d_in, const int* in_sizes, int n_in,
                              void* d_out, int out_size) {
    const float* x  = (const float*)d_in[0];
    const float* W1 = (const float*)d_in[1];
    const float* b1 = (const float*)d_in[2];
    const float* W2 = (const float*)d_in[3];
    const float* b2 = (const float*)d_in[4];
    const float* W3 = (const float*)d_in[5];
    const float* b3 = (const float*)d_in[6];
    const float* W4 = (const float*)d_in[7];
    const float* b4 = (const float*)d_in[8];
    float* out = (float*)d_out;
    const int B = in_sizes[0] / 2;

    prep_w<<<32, 256>>>(W2, W3);

    cudaFuncSetAttribute(pinn_mma_kernel,
                         cudaFuncAttributeMaxDynamicSharedMemorySize, SM_TOT);
    pinn_mma_kernel<<<B / 16, 256, SM_TOT>>>(x, W1, b1, b2, b3, W4, b4, out, B);
}